// round 5
// baseline (speedup 1.0000x reference)
#include <cuda_runtime.h>

#define NBOX   2000
#define MAXDET 10
#define TOPK   5
#define IMG_H  512
#define IMG_W  512
#define NIMG   16
#define CONF_T 0.2f
#define IOU_T  0.4f
#define T1     1024

// scratch for rects: per image, per slot: {valid, x1, y1, x2, y2}
__device__ int g_rect[NIMG * MAXDET * 5];

__device__ __forceinline__ unsigned long long u64max(unsigned long long a, unsigned long long b) {
    return a > b ? a : b;
}

__global__ __launch_bounds__(T1)
void stage1_kernel(const float* __restrict__ region,
                   const float* __restrict__ neg,
                   float* __restrict__ out_tbox,
                   float* __restrict__ out_keep2)
{
    extern __shared__ unsigned char smem[];
    unsigned long long* key = (unsigned long long*)smem;   // NBOX u64, indexed by ORIGINAL idx
    float* bx1 = (float*)(key + NBOX);
    float* by1 = bx1 + NBOX;
    float* bx2 = by1 + NBOX;
    float* by2 = bx2 + NBOX;

    __shared__ int s_hasconf, s_cnt, s_stop;
    __shared__ int s_slot_idx[MAXDET];
    __shared__ float s_slot_conf[MAXDET];
    __shared__ unsigned long long s_wmax[32];
    __shared__ unsigned long long s_win;

    const int b   = blockIdx.x;
    const int tid = threadIdx.x;
    const int wid = tid >> 5;
    const int lid = tid & 31;
    if (tid == 0) { s_hasconf = 0; s_cnt = 0; s_stop = 0; }
    __syncthreads();

    // ---- load boxes, build keys: (score_bits << 32) | (~idx) ----
    const float* rb = region + (long)b * NBOX * 5;
    for (int i = tid; i < NBOX; i += T1) {
        float x1 = rb[i*5+0], y1 = rb[i*5+1];
        float x2 = rb[i*5+2], y2 = rb[i*5+3];
        float cf = rb[i*5+4];
        bx1[i] = x1; by1[i] = y1; bx2[i] = x2; by2[i] = y2;
        key[i] = ((unsigned long long)__float_as_uint(cf) << 32)
               | (unsigned long long)(0xFFFFFFFFu - (unsigned)i);
        if (cf > CONF_T) s_hasconf = 1;
    }
    __syncthreads();

    const bool  hasconf = (s_hasconf != 0);
    const int   cap  = hasconf ? MAXDET : TOPK;
    const float thr0 = hasconf ? CONF_T : 0.0f;

    // invalidate below-threshold boxes
    for (int i = tid; i < NBOX; i += T1) {
        float cf = __uint_as_float((unsigned)(key[i] >> 32));
        if (!(cf > thr0)) key[i] = 0ULL;
    }
    __syncthreads();

    // ---- greedy NMS via iterative argmax; early-exit at cap tiny-kept boxes ----
    while (true) {
        // block argmax over keys (stable descending order == jnp argsort(-scores))
        unsigned long long m = 0ULL;
        for (int j = tid; j < NBOX; j += T1) m = u64max(m, key[j]);
        #pragma unroll
        for (int off = 16; off; off >>= 1)
            m = u64max(m, __shfl_down_sync(0xFFFFFFFFu, m, off));
        if (lid == 0) s_wmax[wid] = m;
        __syncthreads();
        if (wid == 0) {
            m = s_wmax[lid];
            #pragma unroll
            for (int off = 16; off; off >>= 1)
                m = u64max(m, __shfl_down_sync(0xFFFFFFFFu, m, off));
            if (lid == 0) s_win = m;
        }
        __syncthreads();
        unsigned long long win = s_win;
        if (win == 0ULL) break;   // no unsuppressed valid boxes remain

        int   oi  = (int)(0xFFFFFFFFu - (unsigned)(win & 0xFFFFFFFFull));
        float x1i = bx1[oi], y1i = by1[oi], x2i = bx2[oi], y2i = by2[oi];

        if (tid == 0) {
            key[oi] = 0ULL;  // picked: remove from pool
            if (x2i - x1i >= 1.0f && y2i - y1i >= 1.0f) {
                s_slot_idx[s_cnt]  = oi;
                s_slot_conf[s_cnt] = __uint_as_float((unsigned)(win >> 32));
                s_cnt++;
                if (s_cnt >= cap) s_stop = 1;
            }
        }
        __syncthreads();
        if (s_stop) break;

        // suppress overlaps with the picked box
        float ai = fmaxf(x2i - x1i, 0.0f) * fmaxf(y2i - y1i, 0.0f);
        for (int j = tid; j < NBOX; j += T1) {
            unsigned long long kj = key[j];
            if (!kj) continue;
            float x1j = bx1[j], y1j = by1[j], x2j = bx2[j], y2j = by2[j];
            float aj  = fmaxf(x2j - x1j, 0.0f) * fmaxf(y2j - y1j, 0.0f);
            float ix1 = fmaxf(x1i, x1j), iy1 = fmaxf(y1i, y1j);
            float ix2 = fminf(x2i, x2j), iy2 = fminf(y2i, y2j);
            float inter = fmaxf(ix2 - ix1, 0.0f) * fmaxf(iy2 - iy1, 0.0f);
            float iou = inter / (ai + aj - inter + 1e-9f);
            if (iou > IOU_T) key[j] = 0ULL;
        }
        __syncthreads();
    }

    // ---- tiny epilogue: 10-box combine, stable sort, NMS, outputs ----
    if (tid == 0) {
        const float* nb = neg + (long)b * MAXDET * 5;
        float tmp[MAXDET][5];
        int cnt = s_cnt;
        for (int s = 0; s < MAXDET; s++) {
            if (s < cnt) {
                int oi = s_slot_idx[s];
                tmp[s][0] = bx1[oi]; tmp[s][1] = by1[oi];
                tmp[s][2] = bx2[oi]; tmp[s][3] = by2[oi];
                tmp[s][4] = s_slot_conf[s];
            } else {
                for (int f = 0; f < 5; f++) tmp[s][f] = nb[s*5+f];
            }
        }
        // stable insertion sort, descending conf
        int ord[MAXDET];
        for (int s = 0; s < MAXDET; s++) ord[s] = s;
        for (int a = 1; a < MAXDET; a++) {
            int v = ord[a]; float cv = tmp[v][4];
            int c = a - 1;
            while (c >= 0 && tmp[ord[c]][4] < cv) { ord[c+1] = ord[c]; c--; }
            ord[c+1] = v;
        }
        float cbx[MAXDET][5];
        for (int s = 0; s < MAXDET; s++)
            for (int f = 0; f < 5; f++) cbx[s][f] = tmp[ord[s]][f];

        int k2[MAXDET];
        for (int s = 0; s < MAXDET; s++) k2[s] = (cbx[s][4] > 0.0f) ? 1 : 0;
        for (int i2 = 0; i2 < MAXDET; i2++) {
            if (!k2[i2]) continue;
            float ai = fmaxf(cbx[i2][2]-cbx[i2][0],0.f) * fmaxf(cbx[i2][3]-cbx[i2][1],0.f);
            for (int j2 = i2 + 1; j2 < MAXDET; j2++) {
                if (!k2[j2]) continue;
                float aj  = fmaxf(cbx[j2][2]-cbx[j2][0],0.f) * fmaxf(cbx[j2][3]-cbx[j2][1],0.f);
                float ix1 = fmaxf(cbx[i2][0], cbx[j2][0]);
                float iy1 = fmaxf(cbx[i2][1], cbx[j2][1]);
                float ix2 = fminf(cbx[i2][2], cbx[j2][2]);
                float iy2 = fminf(cbx[i2][3], cbx[j2][3]);
                float inter = fmaxf(ix2 - ix1, 0.f) * fmaxf(iy2 - iy1, 0.f);
                float iou = inter / (ai + aj - inter + 1e-9f);
                if (iou > IOU_T) k2[j2] = 0;
            }
        }

        float* tb = out_tbox  + b * (MAXDET * 4);
        float* kk = out_keep2 + b * MAXDET;
        int*   gr = g_rect    + b * (MAXDET * 5);
        for (int s = 0; s < MAXDET; s++) {
            for (int f = 0; f < 4; f++)
                tb[s*4+f] = k2[s] ? cbx[s][f] : 0.0f;
            kk[s] = k2[s] ? 1.0f : 0.0f;
            gr[s*5+0] = k2[s];
            gr[s*5+1] = (int)floorf(cbx[s][0] + 0.5f);
            gr[s*5+2] = (int)floorf(cbx[s][1] + 0.5f);
            gr[s*5+3] = (int)floorf(cbx[s][2] + 0.5f);
            gr[s*5+4] = (int)floorf(cbx[s][3] + 0.5f);
        }
    }
}

__global__ __launch_bounds__(256)
void mask_kernel(float* __restrict__ out_mask)
{
    __shared__ int r[MAXDET * 5];
    __shared__ int s_any;
    const int b   = blockIdx.y;
    const int tid = threadIdx.x;
    if (tid == 0) s_any = 0;
    if (tid < MAXDET * 5) r[tid] = g_rect[b * MAXDET * 5 + tid];
    __syncthreads();

    // this block covers exactly 2 rows: y0, y0+1
    const int y0 = blockIdx.x * 2;
    if (tid < MAXDET) {
        int valid = r[tid*5+0];
        int ry1 = r[tid*5+2], ry2 = r[tid*5+4];
        if (valid && ry2 > y0 && ry1 <= y0 + 1) s_any = 1;
    }
    __syncthreads();

    int t = blockIdx.x * 256 + tid;              // float4 index within image
    long off = (long)b * (IMG_H * IMG_W / 4) + t;

    if (!s_any) {
        ((float4*)out_mask)[off] = make_float4(1.f, 1.f, 1.f, 1.f);
        return;
    }

    int pix = t * 4;
    int y   = pix >> 9;
    int x0  = pix & (IMG_W - 1);

    float m0 = 1.f, m1 = 1.f, m2 = 1.f, m3 = 1.f;
    #pragma unroll
    for (int s = 0; s < MAXDET; s++) {
        int valid = r[s*5+0];
        int rx1 = r[s*5+1], ry1 = r[s*5+2], rx2 = r[s*5+3], ry2 = r[s*5+4];
        if (valid && y >= ry1 && y < ry2) {
            if (x0     >= rx1 && x0     < rx2) m0 = 0.f;
            if (x0 + 1 >= rx1 && x0 + 1 < rx2) m1 = 0.f;
            if (x0 + 2 >= rx1 && x0 + 2 < rx2) m2 = 0.f;
            if (x0 + 3 >= rx1 && x0 + 3 < rx2) m3 = 0.f;
        }
    }
    ((float4*)out_mask)[off] = make_float4(m0, m1, m2, m3);
}

extern "C" void kernel_launch(void* const* d_in, const int* in_sizes, int n_in,
                              void* d_out, int out_size)
{
    // identify inputs by element count (x is unused)
    const float* region = nullptr;
    const float* neg    = nullptr;
    for (int i = 0; i < n_in; i++) {
        if (in_sizes[i] == NIMG * NBOX * 5)        region = (const float*)d_in[i];
        else if (in_sizes[i] == NIMG * MAXDET * 5) neg    = (const float*)d_in[i];
    }

    float* out      = (float*)d_out;
    float* out_mask = out;
    float* out_tbox = out + (long)NIMG * IMG_H * IMG_W;
    float* out_k2   = out_tbox + NIMG * MAXDET * 4;

    size_t smem_sz = (size_t)NBOX * 8 + 4 * (size_t)NBOX * 4;  // keys + coords = 48KB
    cudaFuncSetAttribute(stage1_kernel,
                         cudaFuncAttributeMaxDynamicSharedMemorySize, (int)smem_sz);

    stage1_kernel<<<NIMG, T1, smem_sz>>>(region, neg, out_tbox, out_k2);
    mask_kernel<<<dim3(IMG_H * IMG_W / 4 / 256, NIMG), 256>>>(out_mask);
}

// round 6
// speedup vs baseline: 1.5448x; 1.5448x over previous
#include <cuda_runtime.h>

#define NBOX   2000
#define MAXDET 10
#define TOPK   5
#define IMG_H  512
#define IMG_W  512
#define NIMG   16
#define CONF_T 0.2f
#define IOU_T  0.4f
#define T1     512

// per image, per slot: {x1,y1,x2,y2} rounded ints; invalid slot = {0,0,0,0}
__device__ int4 g_rect4[NIMG * MAXDET];

__device__ __forceinline__ unsigned long long u64max(unsigned long long a, unsigned long long b) {
    return a > b ? a : b;
}

__global__ __launch_bounds__(T1)
void stage1_kernel(const float* __restrict__ region,
                   const float* __restrict__ neg,
                   float* __restrict__ out_tbox,
                   float* __restrict__ out_keep2)
{
    extern __shared__ unsigned char smem[];
    float4* box = (float4*)smem;                               // NBOX float4 (32000B)
    unsigned long long* key = (unsigned long long*)(box + NBOX); // NBOX u64 (16000B)

    __shared__ int s_hasconf;
    __shared__ unsigned long long s_wmax[16];
    __shared__ unsigned long long s_win;

    const int b   = blockIdx.x;
    const int tid = threadIdx.x;
    const int wid = tid >> 5;
    const int lid = tid & 31;
    if (tid == 0) s_hasconf = 0;
    __syncthreads();

    // ---- load boxes via float4, scatter into smem, build keys ----
    const float4* rb4 = (const float4*)(region + (long)b * NBOX * 5);
    int local_has = 0;
    for (int t = tid; t < NBOX * 5 / 4; t += T1) {
        float4 v = rb4[t];
        int f0 = 4 * t;
        #pragma unroll
        for (int c = 0; c < 4; c++) {
            int f    = f0 + c;
            int bidx = f / 5;
            int fld  = f - 5 * bidx;
            float val = (&v.x)[c];
            if (fld == 4) {
                key[bidx] = ((unsigned long long)__float_as_uint(val) << 32)
                          | (unsigned long long)(0xFFFFFFFFu - (unsigned)bidx);
                if (val > CONF_T) local_has = 1;
            } else {
                ((float*)&box[bidx])[fld] = val;
            }
        }
    }
    if (local_has) s_hasconf = 1;
    __syncthreads();

    const bool  hasconf = (s_hasconf != 0);
    const int   cap  = hasconf ? MAXDET : TOPK;
    const float thr0 = hasconf ? CONF_T : 0.0f;

    // invalidate below-threshold keys (same ownership as sweep -> no barrier needed)
    for (int i = tid; i < NBOX; i += T1) {
        float cf = __uint_as_float((unsigned)(key[i] >> 32));
        if (!(cf > thr0)) key[i] = 0ULL;
    }

    // ---- greedy NMS: fused suppress+argmax sweep per pick ----
    int   oi  = -1;
    float x1i = -1e9f, y1i = -1e9f, x2i = -1e9f, y2i = -1e9f, ai = 0.0f;
    int   cnt = 0;
    int   slot_oi[MAXDET];
    float slot_cf[MAXDET];

    while (true) {
        unsigned long long part = 0ULL;
        for (int j = tid; j < NBOX; j += T1) {
            unsigned long long k = key[j];
            if (!k) continue;
            if (j == oi) { key[j] = 0ULL; continue; }
            float4 bb = box[j];
            float aj  = fmaxf(bb.z - bb.x, 0.0f) * fmaxf(bb.w - bb.y, 0.0f);
            float ix1 = fmaxf(x1i, bb.x), iy1 = fmaxf(y1i, bb.y);
            float ix2 = fminf(x2i, bb.z), iy2 = fminf(y2i, bb.w);
            float inter = fmaxf(ix2 - ix1, 0.0f) * fmaxf(iy2 - iy1, 0.0f);
            float iou = inter / (ai + aj - inter + 1e-9f);
            if (iou > IOU_T) key[j] = 0ULL;
            else             part = u64max(part, k);
        }
        // block max-reduce of survivors
        #pragma unroll
        for (int off = 16; off; off >>= 1)
            part = u64max(part, __shfl_down_sync(0xFFFFFFFFu, part, off));
        if (lid == 0) s_wmax[wid] = part;
        __syncthreads();
        if (wid == 0) {
            unsigned long long m = (lid < 16) ? s_wmax[lid] : 0ULL;
            #pragma unroll
            for (int off = 8; off; off >>= 1)
                m = u64max(m, __shfl_down_sync(0xFFFFFFFFu, m, off));
            if (lid == 0) s_win = m;
        }
        __syncthreads();
        unsigned long long win = s_win;
        if (win == 0ULL) break;

        // uniform bookkeeping in every thread (no shared state, no extra barrier)
        oi = (int)(0xFFFFFFFFu - (unsigned)(win & 0xFFFFFFFFull));
        float4 pb = box[oi];
        x1i = pb.x; y1i = pb.y; x2i = pb.z; y2i = pb.w;
        ai = fmaxf(x2i - x1i, 0.0f) * fmaxf(y2i - y1i, 0.0f);
        if (x2i - x1i >= 1.0f && y2i - y1i >= 1.0f) {
            if (tid == 0) {
                slot_oi[cnt] = oi;
                slot_cf[cnt] = __uint_as_float((unsigned)(win >> 32));
            }
            cnt++;
            if (cnt >= cap) break;
        }
    }

    // ---- tiny epilogue (tid0-local state; box[] written pre-barrier) ----
    if (tid == 0) {
        const float* nb = neg + (long)b * MAXDET * 5;
        float tmp[MAXDET][5];
        for (int s = 0; s < MAXDET; s++) {
            if (s < cnt) {
                int o = slot_oi[s];
                float4 bb = box[o];
                tmp[s][0] = bb.x; tmp[s][1] = bb.y;
                tmp[s][2] = bb.z; tmp[s][3] = bb.w;
                tmp[s][4] = slot_cf[s];
            } else {
                for (int f = 0; f < 5; f++) tmp[s][f] = nb[s*5+f];
            }
        }
        // stable insertion sort, descending conf
        int ord[MAXDET];
        for (int s = 0; s < MAXDET; s++) ord[s] = s;
        for (int a = 1; a < MAXDET; a++) {
            int v = ord[a]; float cv = tmp[v][4];
            int c = a - 1;
            while (c >= 0 && tmp[ord[c]][4] < cv) { ord[c+1] = ord[c]; c--; }
            ord[c+1] = v;
        }
        float cbx[MAXDET][5];
        for (int s = 0; s < MAXDET; s++)
            for (int f = 0; f < 5; f++) cbx[s][f] = tmp[ord[s]][f];

        int k2[MAXDET];
        for (int s = 0; s < MAXDET; s++) k2[s] = (cbx[s][4] > 0.0f) ? 1 : 0;
        for (int i2 = 0; i2 < MAXDET; i2++) {
            if (!k2[i2]) continue;
            float aa = fmaxf(cbx[i2][2]-cbx[i2][0],0.f) * fmaxf(cbx[i2][3]-cbx[i2][1],0.f);
            for (int j2 = i2 + 1; j2 < MAXDET; j2++) {
                if (!k2[j2]) continue;
                float aj  = fmaxf(cbx[j2][2]-cbx[j2][0],0.f) * fmaxf(cbx[j2][3]-cbx[j2][1],0.f);
                float ix1 = fmaxf(cbx[i2][0], cbx[j2][0]);
                float iy1 = fmaxf(cbx[i2][1], cbx[j2][1]);
                float ix2 = fminf(cbx[i2][2], cbx[j2][2]);
                float iy2 = fminf(cbx[i2][3], cbx[j2][3]);
                float inter = fmaxf(ix2 - ix1, 0.f) * fmaxf(iy2 - iy1, 0.f);
                float iou = inter / (aa + aj - inter + 1e-9f);
                if (iou > IOU_T) k2[j2] = 0;
            }
        }

        float* tb = out_tbox  + b * (MAXDET * 4);
        float* kk = out_keep2 + b * MAXDET;
        for (int s = 0; s < MAXDET; s++) {
            for (int f = 0; f < 4; f++)
                tb[s*4+f] = k2[s] ? cbx[s][f] : 0.0f;
            kk[s] = k2[s] ? 1.0f : 0.0f;
            int4 r;
            if (k2[s]) {
                r.x = (int)floorf(cbx[s][0] + 0.5f);
                r.y = (int)floorf(cbx[s][1] + 0.5f);
                r.z = (int)floorf(cbx[s][2] + 0.5f);
                r.w = (int)floorf(cbx[s][3] + 0.5f);
            } else {
                r.x = 0; r.y = 0; r.z = 0; r.w = 0;   // y < r.w never true
            }
            g_rect4[b * MAXDET + s] = r;
        }
    }
}

__global__ __launch_bounds__(256)
void mask_kernel(float* __restrict__ out_mask)
{
    __shared__ int4 r[MAXDET];
    const int b   = blockIdx.y;
    const int tid = threadIdx.x;
    if (tid < MAXDET) r[tid] = g_rect4[b * MAXDET + tid];
    __syncthreads();

    int t   = blockIdx.x * 256 + tid;   // 8-pixel group index within image
    int pix = t * 8;
    int y   = pix >> 9;                 // IMG_W = 512
    int x0  = pix & (IMG_W - 1);

    unsigned cover = 0;
    #pragma unroll
    for (int s = 0; s < MAXDET; s++) {
        int4 rr = r[s];
        if (y >= rr.y && y < rr.w) {
            int st = max(rr.x - x0, 0);
            int en = min(rr.z - x0, 8);
            if (en > st) cover |= ((1u << en) - (1u << st));
        }
    }
    float m0 = (cover & 1u)   ? 0.f : 1.f;
    float m1 = (cover & 2u)   ? 0.f : 1.f;
    float m2 = (cover & 4u)   ? 0.f : 1.f;
    float m3 = (cover & 8u)   ? 0.f : 1.f;
    float m4 = (cover & 16u)  ? 0.f : 1.f;
    float m5 = (cover & 32u)  ? 0.f : 1.f;
    float m6 = (cover & 64u)  ? 0.f : 1.f;
    float m7 = (cover & 128u) ? 0.f : 1.f;

    float* dst = out_mask + ((long)b << 18) + pix;   // 512*512 = 1<<18
    asm volatile("st.global.v8.f32 [%0], {%1,%2,%3,%4,%5,%6,%7,%8};"
                 :: "l"(dst),
                    "f"(m0), "f"(m1), "f"(m2), "f"(m3),
                    "f"(m4), "f"(m5), "f"(m6), "f"(m7)
                 : "memory");
}

extern "C" void kernel_launch(void* const* d_in, const int* in_sizes, int n_in,
                              void* d_out, int out_size)
{
    // identify inputs by element count (x is unused)
    const float* region = nullptr;
    const float* neg    = nullptr;
    for (int i = 0; i < n_in; i++) {
        if (in_sizes[i] == NIMG * NBOX * 5)        region = (const float*)d_in[i];
        else if (in_sizes[i] == NIMG * MAXDET * 5) neg    = (const float*)d_in[i];
    }

    float* out      = (float*)d_out;
    float* out_mask = out;
    float* out_tbox = out + (long)NIMG * IMG_H * IMG_W;
    float* out_k2   = out_tbox + NIMG * MAXDET * 4;

    size_t smem_sz = (size_t)NBOX * 16 + (size_t)NBOX * 8;  // box float4 + key u64 = 48000B
    cudaFuncSetAttribute(stage1_kernel,
                         cudaFuncAttributeMaxDynamicSharedMemorySize, (int)smem_sz);

    stage1_kernel<<<NIMG, T1, smem_sz>>>(region, neg, out_tbox, out_k2);
    mask_kernel<<<dim3(IMG_H * IMG_W / 8 / 256, NIMG), 256>>>(out_mask);
}

// round 7
// speedup vs baseline: 2.0435x; 1.3228x over previous
#include <cuda_runtime.h>

#define NBOX   2000
#define MAXDET 10
#define TOPK   5
#define IMG_H  512
#define IMG_W  512
#define NIMG   16
#define CONF_T 0.2f
#define IOU_T  0.4f
#define T1     512
#define NCAND  64

// per image, per slot: {x1,y1,x2,y2} rounded ints; invalid slot = {0,0,0,0}
__device__ int4 g_rect4[NIMG * MAXDET];

__device__ __forceinline__ unsigned long long u64max(unsigned long long a, unsigned long long b) {
    return a > b ? a : b;
}

// shared epilogue: combine picks with neg boxes, stable sort, small NMS, outputs
__device__ __forceinline__ void epilogue(int b, int cnt,
                                         const float4* pkb, const float* pkc,
                                         const float* __restrict__ neg,
                                         float* __restrict__ out_tbox,
                                         float* __restrict__ out_keep2)
{
    const float* nb = neg + (long)b * MAXDET * 5;
    float tmp[MAXDET][5];
    for (int s = 0; s < MAXDET; s++) {
        if (s < cnt) {
            tmp[s][0] = pkb[s].x; tmp[s][1] = pkb[s].y;
            tmp[s][2] = pkb[s].z; tmp[s][3] = pkb[s].w;
            tmp[s][4] = pkc[s];
        } else {
            for (int f = 0; f < 5; f++) tmp[s][f] = nb[s*5+f];
        }
    }
    int ord[MAXDET];
    for (int s = 0; s < MAXDET; s++) ord[s] = s;
    for (int a = 1; a < MAXDET; a++) {
        int v = ord[a]; float cv = tmp[v][4];
        int c = a - 1;
        while (c >= 0 && tmp[ord[c]][4] < cv) { ord[c+1] = ord[c]; c--; }
        ord[c+1] = v;
    }
    float cbx[MAXDET][5];
    for (int s = 0; s < MAXDET; s++)
        for (int f = 0; f < 5; f++) cbx[s][f] = tmp[ord[s]][f];

    int k2[MAXDET];
    for (int s = 0; s < MAXDET; s++) k2[s] = (cbx[s][4] > 0.0f) ? 1 : 0;
    for (int i2 = 0; i2 < MAXDET; i2++) {
        if (!k2[i2]) continue;
        float aa = fmaxf(cbx[i2][2]-cbx[i2][0],0.f) * fmaxf(cbx[i2][3]-cbx[i2][1],0.f);
        for (int j2 = i2 + 1; j2 < MAXDET; j2++) {
            if (!k2[j2]) continue;
            float aj  = fmaxf(cbx[j2][2]-cbx[j2][0],0.f) * fmaxf(cbx[j2][3]-cbx[j2][1],0.f);
            float ix1 = fmaxf(cbx[i2][0], cbx[j2][0]);
            float iy1 = fmaxf(cbx[i2][1], cbx[j2][1]);
            float ix2 = fminf(cbx[i2][2], cbx[j2][2]);
            float iy2 = fminf(cbx[i2][3], cbx[j2][3]);
            float inter = fmaxf(ix2 - ix1, 0.f) * fmaxf(iy2 - iy1, 0.f);
            float iou = inter / (aa + aj - inter + 1e-9f);
            if (iou > IOU_T) k2[j2] = 0;
        }
    }

    float* tb = out_tbox  + b * (MAXDET * 4);
    float* kk = out_keep2 + b * MAXDET;
    for (int s = 0; s < MAXDET; s++) {
        for (int f = 0; f < 4; f++)
            tb[s*4+f] = k2[s] ? cbx[s][f] : 0.0f;
        kk[s] = k2[s] ? 1.0f : 0.0f;
        int4 r;
        if (k2[s]) {
            r.x = (int)floorf(cbx[s][0] + 0.5f);
            r.y = (int)floorf(cbx[s][1] + 0.5f);
            r.z = (int)floorf(cbx[s][2] + 0.5f);
            r.w = (int)floorf(cbx[s][3] + 0.5f);
        } else {
            r.x = 0; r.y = 0; r.z = 0; r.w = 0;
        }
        g_rect4[b * MAXDET + s] = r;
    }
}

__global__ __launch_bounds__(T1)
void stage1_kernel(const float* __restrict__ region,
                   const float* __restrict__ neg,
                   float* __restrict__ out_tbox,
                   float* __restrict__ out_keep2)
{
    // dynamic smem only used by the (rare) fallback path
    extern __shared__ unsigned char dyn[];
    unsigned long long* fb_key = (unsigned long long*)dyn;   // NBOX u64
    float4*             fb_box = (float4*)(fb_key + NBOX);   // NBOX float4

    __shared__ int s_hist[13];
    __shared__ float s_T;
    __shared__ int s_fb, s_complete, s_hasconf, s_ncand;
    __shared__ unsigned long long s_ck[NCAND];
    __shared__ float4 s_cbox[NCAND];
    __shared__ unsigned long long s_sup[NCAND];   // suppression bitmask rows (by slot)
    __shared__ unsigned long long s_sk[NCAND];    // sorted keys
    __shared__ int s_ss[NCAND];                   // sorted slot ids
    __shared__ unsigned long long s_wmax[16];
    __shared__ unsigned long long s_win;

    const float LAD[13] = {0.991f, 0.9865f, 0.980f, 0.970f, 0.954f, 0.932f,
                           0.897f, 0.846f, 0.769f, 0.654f, 0.481f, 0.221f, CONF_T};

    const int b   = blockIdx.x;
    const int tid = threadIdx.x;
    const int wid = tid >> 5;
    const int lid = tid & 31;
    const float* rb = region + (long)b * NBOX * 5;

    float4 pk_box[MAXDET];
    float  pk_cf[MAXDET];
    int    pcnt = 0;

    if (tid < 13) s_hist[tid] = 0;
    if (tid == 0) { s_fb = 0; s_complete = 0; s_hasconf = 0; s_ncand = 0; }
    __syncthreads();

    // ---- phase 1: histogram confidences over ladder ----
    for (int i = tid; i < NBOX; i += T1) {
        float cf = rb[i*5+4];
        if (cf > CONF_T) {
            s_hasconf = 1;
            int bk = 12;
            #pragma unroll
            for (int k = 11; k >= 0; k--) if (cf > LAD[k]) bk = k;
            atomicAdd(&s_hist[bk], 1);
        }
    }
    __syncthreads();

    // ---- phase 2: choose threshold ----
    if (tid == 0) {
        if (!s_hasconf) { s_fb = 1; s_T = 2.0f; }
        else {
            int suf = 0, prev = 0, chosen = -1, complete = 0, crossed = 0;
            for (int k = 0; k < 13; k++) {
                prev = suf; suf += s_hist[k];
                if (suf >= 24) {
                    crossed = 1;
                    if (suf <= NCAND) { chosen = k; complete = (k == 12); }
                    else if (k > 0 && prev >= 12) { chosen = k - 1; }
                    break;
                }
            }
            if (!crossed) { chosen = 12; complete = 1; }   // few valid boxes: take all
            if (chosen < 0) { s_fb = 1; s_T = 2.0f; }
            else { s_T = LAD[chosen]; s_complete = complete; }
        }
    }
    __syncthreads();

    // ---- phase 3: compact candidates (conf > T) ----
    {
        float T = s_T;
        for (int i = tid; i < NBOX; i += T1) {
            float cf = rb[i*5+4];
            if (cf > T) {
                int p = atomicAdd(&s_ncand, 1);
                if (p < NCAND) {
                    s_ck[p] = ((unsigned long long)__float_as_uint(cf) << 32)
                            | (unsigned long long)(0xFFFFFFFFu - (unsigned)i);
                    s_cbox[p] = make_float4(rb[i*5+0], rb[i*5+1], rb[i*5+2], rb[i*5+3]);
                }
            }
        }
    }
    __syncthreads();

    // ---- phase 4: suppression matrix (byte per thread, no atomics) + sort init ----
    {
        int nc = min(s_ncand, NCAND);
        if (tid < NCAND) { s_sk[tid] = (tid < nc) ? s_ck[tid] : 0ULL; s_ss[tid] = tid; }
        int i  = tid >> 3;
        int j0 = (tid & 7) << 3;
        unsigned char byte = 0;
        if (i < nc) {
            float4 bi = s_cbox[i];
            float ai = fmaxf(bi.z - bi.x, 0.f) * fmaxf(bi.w - bi.y, 0.f);
            #pragma unroll
            for (int jj = 0; jj < 8; jj++) {
                int j = j0 + jj;
                if (j < nc) {
                    float4 bj = s_cbox[j];
                    float aj  = fmaxf(bj.z - bj.x, 0.f) * fmaxf(bj.w - bj.y, 0.f);
                    float ix1 = fmaxf(bi.x, bj.x), iy1 = fmaxf(bi.y, bj.y);
                    float ix2 = fminf(bi.z, bj.z), iy2 = fminf(bi.w, bj.w);
                    float inter = fmaxf(ix2 - ix1, 0.f) * fmaxf(iy2 - iy1, 0.f);
                    float iou = inter / (ai + aj - inter + 1e-9f);
                    if (iou > IOU_T) byte |= (unsigned char)(1 << jj);
                }
            }
        }
        ((unsigned char*)s_sup)[tid] = byte;
    }
    __syncthreads();

    // ---- phase 5: bitonic sort 64 keys descending (with slot payload) ----
    for (int k = 2; k <= NCAND; k <<= 1) {
        for (int j = k >> 1; j > 0; j >>= 1) {
            if (tid < NCAND) {
                int i = tid, ixj = i ^ j;
                if (ixj > i) {
                    unsigned long long a = s_sk[i], c = s_sk[ixj];
                    bool up = ((i & k) == 0);
                    if (up ? (a < c) : (a > c)) {
                        s_sk[i] = c; s_sk[ixj] = a;
                        int t2 = s_ss[i]; s_ss[i] = s_ss[ixj]; s_ss[ixj] = t2;
                    }
                }
            }
            __syncthreads();
        }
    }

    // ---- phase 6: serial greedy scan with bitmask kills (tid 0) ----
    if (tid == 0 && !s_fb) {
        int nc = s_ncand;
        if (nc > NCAND) s_fb = 1;
        else {
            unsigned long long alive = (nc >= 64) ? ~0ULL : ((1ULL << nc) - 1ULL);
            int done = 0;
            for (int s = 0; s < nc; s++) {
                int u = s_ss[s];
                if (!((alive >> u) & 1ULL)) continue;
                float4 bb = s_cbox[u];
                alive &= ~s_sup[u];
                alive &= ~(1ULL << u);
                if (bb.z - bb.x >= 1.0f && bb.w - bb.y >= 1.0f) {
                    pk_box[pcnt] = bb;
                    pk_cf[pcnt]  = __uint_as_float((unsigned)(s_sk[s] >> 32));
                    pcnt++;
                    if (pcnt >= MAXDET) { done = 1; break; }
                }
            }
            if (!done && !s_complete) s_fb = 1;  // pool incomplete & cap not reached
        }
    }
    __syncthreads();

    if (s_fb) {
        // ================= FALLBACK: full iterative-argmax greedy NMS =================
        const bool  hasconf = (s_hasconf != 0);
        const int   cap  = hasconf ? MAXDET : TOPK;
        const float thr0 = hasconf ? CONF_T : 0.0f;

        for (int i = tid; i < NBOX; i += T1) {
            float x1 = rb[i*5+0], y1 = rb[i*5+1];
            float x2 = rb[i*5+2], y2 = rb[i*5+3];
            float cf = rb[i*5+4];
            fb_box[i] = make_float4(x1, y1, x2, y2);
            fb_key[i] = (cf > thr0)
                ? (((unsigned long long)__float_as_uint(cf) << 32)
                   | (unsigned long long)(0xFFFFFFFFu - (unsigned)i))
                : 0ULL;
        }
        __syncthreads();

        int   oi  = -1;
        float x1i = -1e9f, y1i = -1e9f, x2i = -1e9f, y2i = -1e9f, ai = 0.0f;
        int   cnt = 0;
        pcnt = 0;

        while (true) {
            unsigned long long part = 0ULL;
            for (int j = tid; j < NBOX; j += T1) {
                unsigned long long k = fb_key[j];
                if (!k) continue;
                if (j == oi) { fb_key[j] = 0ULL; continue; }
                float4 bb = fb_box[j];
                float aj  = fmaxf(bb.z - bb.x, 0.0f) * fmaxf(bb.w - bb.y, 0.0f);
                float ix1 = fmaxf(x1i, bb.x), iy1 = fmaxf(y1i, bb.y);
                float ix2 = fminf(x2i, bb.z), iy2 = fminf(y2i, bb.w);
                float inter = fmaxf(ix2 - ix1, 0.0f) * fmaxf(iy2 - iy1, 0.0f);
                float iou = inter / (ai + aj - inter + 1e-9f);
                if (iou > IOU_T) fb_key[j] = 0ULL;
                else             part = u64max(part, k);
            }
            #pragma unroll
            for (int off = 16; off; off >>= 1)
                part = u64max(part, __shfl_down_sync(0xFFFFFFFFu, part, off));
            if (lid == 0) s_wmax[wid] = part;
            __syncthreads();
            if (wid == 0) {
                unsigned long long m = (lid < 16) ? s_wmax[lid] : 0ULL;
                #pragma unroll
                for (int off = 8; off; off >>= 1)
                    m = u64max(m, __shfl_down_sync(0xFFFFFFFFu, m, off));
                if (lid == 0) s_win = m;
            }
            __syncthreads();
            unsigned long long win = s_win;
            if (win == 0ULL) break;

            oi = (int)(0xFFFFFFFFu - (unsigned)(win & 0xFFFFFFFFull));
            float4 pb = fb_box[oi];
            x1i = pb.x; y1i = pb.y; x2i = pb.z; y2i = pb.w;
            ai = fmaxf(x2i - x1i, 0.0f) * fmaxf(y2i - y1i, 0.0f);
            if (x2i - x1i >= 1.0f && y2i - y1i >= 1.0f) {
                if (tid == 0) {
                    pk_box[cnt] = pb;
                    pk_cf[cnt]  = __uint_as_float((unsigned)(win >> 32));
                }
                cnt++;
                if (cnt >= cap) break;
            }
        }
        pcnt = cnt;
        if (tid == 0) epilogue(b, pcnt, pk_box, pk_cf, neg, out_tbox, out_keep2);
    } else {
        if (tid == 0) epilogue(b, pcnt, pk_box, pk_cf, neg, out_tbox, out_keep2);
    }
}

__global__ __launch_bounds__(256)
void mask_kernel(float* __restrict__ out_mask)
{
    __shared__ int4 r[MAXDET];
    const int b   = blockIdx.y;
    const int tid = threadIdx.x;
    if (tid < MAXDET) r[tid] = g_rect4[b * MAXDET + tid];
    __syncthreads();

    int t   = blockIdx.x * 256 + tid;   // 16-pixel group index within image
    int pix = t * 16;
    int y   = pix >> 9;                 // IMG_W = 512
    int x0  = pix & (IMG_W - 1);

    unsigned cover = 0;
    #pragma unroll
    for (int s = 0; s < MAXDET; s++) {
        int4 rr = r[s];
        if (y >= rr.y && y < rr.w) {
            int st = max(rr.x - x0, 0);
            int en = min(rr.z - x0, 16);
            if (en > st) cover |= ((1u << en) - (1u << st));
        }
    }

    float m[16];
    #pragma unroll
    for (int c = 0; c < 16; c++) m[c] = (cover >> c & 1u) ? 0.f : 1.f;

    float* dst = out_mask + ((long)b << 18) + pix;   // 512*512 = 1<<18
    asm volatile("st.global.v8.f32 [%0], {%1,%2,%3,%4,%5,%6,%7,%8};"
                 :: "l"(dst),
                    "f"(m[0]), "f"(m[1]), "f"(m[2]), "f"(m[3]),
                    "f"(m[4]), "f"(m[5]), "f"(m[6]), "f"(m[7])
                 : "memory");
    asm volatile("st.global.v8.f32 [%0], {%1,%2,%3,%4,%5,%6,%7,%8};"
                 :: "l"(dst + 8),
                    "f"(m[8]),  "f"(m[9]),  "f"(m[10]), "f"(m[11]),
                    "f"(m[12]), "f"(m[13]), "f"(m[14]), "f"(m[15])
                 : "memory");
}

extern "C" void kernel_launch(void* const* d_in, const int* in_sizes, int n_in,
                              void* d_out, int out_size)
{
    const float* region = nullptr;
    const float* neg    = nullptr;
    for (int i = 0; i < n_in; i++) {
        if (in_sizes[i] == NIMG * NBOX * 5)        region = (const float*)d_in[i];
        else if (in_sizes[i] == NIMG * MAXDET * 5) neg    = (const float*)d_in[i];
    }

    float* out      = (float*)d_out;
    float* out_mask = out;
    float* out_tbox = out + (long)NIMG * IMG_H * IMG_W;
    float* out_k2   = out_tbox + NIMG * MAXDET * 4;

    size_t smem_sz = (size_t)NBOX * 8 + (size_t)NBOX * 16;  // fallback arrays, 48000B
    cudaFuncSetAttribute(stage1_kernel,
                         cudaFuncAttributeMaxDynamicSharedMemorySize, (int)smem_sz);

    stage1_kernel<<<NIMG, T1, smem_sz>>>(region, neg, out_tbox, out_k2);
    mask_kernel<<<dim3(IMG_H * IMG_W / 16 / 256, NIMG), 256>>>(out_mask);
}

// round 9
// speedup vs baseline: 2.8702x; 1.4046x over previous
#include <cuda_runtime.h>

#define NBOX   2000
#define MAXDET 10
#define TOPK   5
#define IMG_H  512
#define IMG_W  512
#define NIMG   16
#define CONF_T 0.2f
#define IOU_T  0.4f
#define TB     512
#define NCAND  64
#define MASK_BLOCKS_PER_IMG 32   // 512 thr * 16 px * 32 = 262144 px

// per image, per slot: {x1,y1,x2,y2} rounded ints; invalid slot = {0,0,0,0}
__device__ int4 g_rect4[NIMG * MAXDET];
__device__ unsigned g_done[NIMG];            // zero-init; idempotent across replays

// fallback scratch (rare path) in global memory
__device__ unsigned long long g_fbkey[NIMG][NBOX];
__device__ float4             g_fbbox[NIMG][NBOX];

__device__ __forceinline__ unsigned long long u64max(unsigned long long a, unsigned long long b) {
    return a > b ? a : b;
}

// epilogue: combine picks with neg boxes, stable sort, small NMS, outputs
__device__ __forceinline__ void epilogue(int b, int cnt,
                                         const float4* pkb, const float* pkc,
                                         const float* __restrict__ neg,
                                         float* __restrict__ out_tbox,
                                         float* __restrict__ out_keep2)
{
    const float* nb = neg + (long)b * MAXDET * 5;
    float tmp[MAXDET][5];
    for (int s = 0; s < MAXDET; s++) {
        if (s < cnt) {
            tmp[s][0] = pkb[s].x; tmp[s][1] = pkb[s].y;
            tmp[s][2] = pkb[s].z; tmp[s][3] = pkb[s].w;
            tmp[s][4] = pkc[s];
        } else {
            for (int f = 0; f < 5; f++) tmp[s][f] = nb[s*5+f];
        }
    }
    int ord[MAXDET];
    for (int s = 0; s < MAXDET; s++) ord[s] = s;
    for (int a = 1; a < MAXDET; a++) {
        int v = ord[a]; float cv = tmp[v][4];
        int c = a - 1;
        while (c >= 0 && tmp[ord[c]][4] < cv) { ord[c+1] = ord[c]; c--; }
        ord[c+1] = v;
    }
    float cbx[MAXDET][5];
    for (int s = 0; s < MAXDET; s++)
        for (int f = 0; f < 5; f++) cbx[s][f] = tmp[ord[s]][f];

    int k2[MAXDET];
    for (int s = 0; s < MAXDET; s++) k2[s] = (cbx[s][4] > 0.0f) ? 1 : 0;
    for (int i2 = 0; i2 < MAXDET; i2++) {
        if (!k2[i2]) continue;
        float aa = fmaxf(cbx[i2][2]-cbx[i2][0],0.f) * fmaxf(cbx[i2][3]-cbx[i2][1],0.f);
        for (int j2 = i2 + 1; j2 < MAXDET; j2++) {
            if (!k2[j2]) continue;
            float ix1 = fmaxf(cbx[i2][0], cbx[j2][0]);
            float iy1 = fmaxf(cbx[i2][1], cbx[j2][1]);
            float ix2 = fminf(cbx[i2][2], cbx[j2][2]);
            float iy2 = fminf(cbx[i2][3], cbx[j2][3]);
            float inter = fmaxf(ix2 - ix1, 0.f) * fmaxf(iy2 - iy1, 0.f);
            if (inter > 0.f) {   // div only when it can matter
                float aj = fmaxf(cbx[j2][2]-cbx[j2][0],0.f) * fmaxf(cbx[j2][3]-cbx[j2][1],0.f);
                float iou = inter / (aa + aj - inter + 1e-9f);
                if (iou > IOU_T) k2[j2] = 0;
            }
        }
    }

    float* tb = out_tbox  + b * (MAXDET * 4);
    float* kk = out_keep2 + b * MAXDET;
    for (int s = 0; s < MAXDET; s++) {
        for (int f = 0; f < 4; f++)
            tb[s*4+f] = k2[s] ? cbx[s][f] : 0.0f;
        kk[s] = k2[s] ? 1.0f : 0.0f;
        int4 r;
        if (k2[s]) {
            r.x = (int)floorf(cbx[s][0] + 0.5f);
            r.y = (int)floorf(cbx[s][1] + 0.5f);
            r.z = (int)floorf(cbx[s][2] + 0.5f);
            r.w = (int)floorf(cbx[s][3] + 0.5f);
        } else {
            r.x = 0; r.y = 0; r.z = 0; r.w = 0;
        }
        g_rect4[b * MAXDET + s] = r;
    }
}

__global__ __launch_bounds__(TB)
void fused_kernel(const float* __restrict__ region,
                  const float* __restrict__ neg,
                  float* __restrict__ out_mask,
                  float* __restrict__ out_tbox,
                  float* __restrict__ out_keep2)
{
    const int bid = blockIdx.x;
    const int tid = threadIdx.x;

    if (bid >= NIMG) {
        // ======================= MASK BLOCK =======================
        __shared__ int4 s_r[MAXDET];
        const int mb  = bid - NIMG;
        const int b   = mb >> 5;              // 32 blocks per image
        const int blk = mb & 31;

        if (tid == 0) {
            while (atomicAdd(&g_done[b], 0u) == 0u) __nanosleep(64);
        }
        __syncthreads();
        __threadfence();
        if (tid < MAXDET) s_r[tid] = g_rect4[b * MAXDET + tid];
        __syncthreads();

        int t   = blk * TB + tid;
        int pix = t * 16;
        int y   = pix >> 9;
        int x0  = pix & (IMG_W - 1);

        unsigned cover = 0;
        #pragma unroll
        for (int s = 0; s < MAXDET; s++) {
            int4 rr = s_r[s];
            if (y >= rr.y && y < rr.w) {
                int st = max(rr.x - x0, 0);
                int en = min(rr.z - x0, 16);
                if (en > st) cover |= ((1u << en) - (1u << st));
            }
        }
        float m[16];
        #pragma unroll
        for (int c = 0; c < 16; c++) m[c] = (cover >> c & 1u) ? 0.f : 1.f;

        float* dst = out_mask + ((long)b << 18) + pix;
        asm volatile("st.global.v8.f32 [%0], {%1,%2,%3,%4,%5,%6,%7,%8};"
                     :: "l"(dst),
                        "f"(m[0]), "f"(m[1]), "f"(m[2]), "f"(m[3]),
                        "f"(m[4]), "f"(m[5]), "f"(m[6]), "f"(m[7]) : "memory");
        asm volatile("st.global.v8.f32 [%0], {%1,%2,%3,%4,%5,%6,%7,%8};"
                     :: "l"(dst + 8),
                        "f"(m[8]),  "f"(m[9]),  "f"(m[10]), "f"(m[11]),
                        "f"(m[12]), "f"(m[13]), "f"(m[14]), "f"(m[15]) : "memory");
        return;
    }

    // ======================= STAGE-1 BLOCK =======================
    __shared__ float s_conf[NBOX];
    __shared__ int s_hist[13];
    __shared__ float s_T;
    __shared__ int s_fb, s_complete, s_hasconf, s_ncand;
    __shared__ unsigned long long s_ck[NCAND];
    __shared__ float4 s_cbox[NCAND];
    __shared__ unsigned long long s_skey[NCAND];
    __shared__ float4 s_sbox[NCAND];
    __shared__ unsigned long long s_sup[NCAND];
    __shared__ unsigned char s_tinyb[NCAND];
    __shared__ unsigned long long s_wmax[16];
    __shared__ unsigned long long s_win;

    const float LAD[13] = {0.991f, 0.9865f, 0.980f, 0.970f, 0.954f, 0.932f,
                           0.897f, 0.846f, 0.769f, 0.654f, 0.481f, 0.221f, CONF_T};

    const int b   = bid;
    const int wid = tid >> 5;
    const int lid = tid & 31;
    const float* rb = region + (long)b * NBOX * 5;

    float4 pk_box[MAXDET];
    float  pk_cf[MAXDET];
    int    pcnt = 0;

    if (tid < 13) s_hist[tid] = 0;
    if (tid == 0) { s_fb = 0; s_complete = 0; s_hasconf = 0; s_ncand = 0; }
    __syncthreads();

    // ---- phase 1: load confs to smem + ballot histogram ----
    for (int base = 0; base < 2048; base += TB) {
        int i = base + tid;
        float cf = -1.0f;
        if (i < NBOX) { cf = rb[i*5+4]; s_conf[i] = cf; }
        bool valid = (cf > CONF_T);
        unsigned anyb = __ballot_sync(0xFFFFFFFFu, valid);
        if (anyb && lid == 0) s_hasconf = 1;
        int bk = -1;
        if (valid) {
            bk = 12;
            #pragma unroll
            for (int k = 11; k >= 0; k--) if (cf > LAD[k]) bk = k;
        }
        #pragma unroll
        for (int k = 0; k < 13; k++) {
            unsigned mm = __ballot_sync(0xFFFFFFFFu, bk == k);
            if (lid == 0 && mm) atomicAdd(&s_hist[k], __popc(mm));
        }
    }
    __syncthreads();

    // ---- phase 2: choose threshold ----
    if (tid == 0) {
        if (!s_hasconf) { s_fb = 1; s_T = 2.0f; }
        else {
            int suf = 0, prev = 0, chosen = -1, complete = 0, crossed = 0;
            for (int k = 0; k < 13; k++) {
                prev = suf; suf += s_hist[k];
                if (suf >= 24) {
                    crossed = 1;
                    if (suf <= NCAND) { chosen = k; complete = (k == 12); }
                    else if (k > 0 && prev >= 12) { chosen = k - 1; }
                    break;
                }
            }
            if (!crossed) { chosen = 12; complete = 1; }
            if (chosen < 0) { s_fb = 1; s_T = 2.0f; }
            else { s_T = LAD[chosen]; s_complete = complete; }
        }
    }
    __syncthreads();

    // ---- phase 3: compact candidates (conf from smem) ----
    {
        float T = s_T;
        for (int i = tid; i < NBOX; i += TB) {
            float cf = s_conf[i];
            if (cf > T) {
                int p = atomicAdd(&s_ncand, 1);
                if (p < NCAND) {
                    s_ck[p] = ((unsigned long long)__float_as_uint(cf) << 32)
                            | (unsigned long long)(0xFFFFFFFFu - (unsigned)i);
                    s_cbox[p] = make_float4(rb[i*5+0], rb[i*5+1], rb[i*5+2], rb[i*5+3]);
                }
            }
        }
    }
    __syncthreads();

    int nc = min(s_ncand, NCAND);

    // ---- phase 4: rank sort (keys distinct) ----
    if (tid < NCAND) {
        unsigned long long mykey = (tid < nc) ? s_ck[tid] : 0ULL;
        int rank = 0;
        for (int j = 0; j < nc; j++) rank += (s_ck[j] > mykey) ? 1 : 0;
        if (tid < nc) {
            s_skey[rank] = mykey;
            float4 bb = s_cbox[tid];
            s_sbox[rank]  = bb;
            s_tinyb[rank] = (bb.z - bb.x >= 1.0f && bb.w - bb.y >= 1.0f) ? 1 : 0;
        }
    }
    __syncthreads();

    // ---- phase 5: suppression matrix in sorted space (ballot rows, div-skip) ----
    for (int t = wid; t < 2 * NCAND; t += 16) {
        int row = t >> 1, colbase = (t & 1) << 5;
        bool bit = false;
        if (row < nc) {
            float4 bi = s_sbox[row];
            float ai = fmaxf(bi.z - bi.x, 0.f) * fmaxf(bi.w - bi.y, 0.f);
            int col = colbase + lid;
            if (col < nc) {
                float4 bj = s_sbox[col];
                float ix1 = fmaxf(bi.x, bj.x), iy1 = fmaxf(bi.y, bj.y);
                float ix2 = fminf(bi.z, bj.z), iy2 = fminf(bi.w, bj.w);
                float inter = fmaxf(ix2 - ix1, 0.f) * fmaxf(iy2 - iy1, 0.f);
                if (inter > 0.f) {
                    float aj  = fmaxf(bj.z - bj.x, 0.f) * fmaxf(bj.w - bj.y, 0.f);
                    float iou = inter / (ai + aj - inter + 1e-9f);
                    bit = (iou > IOU_T);
                }
            }
        }
        unsigned mm = __ballot_sync(0xFFFFFFFFu, bit);
        if (lid == 0) ((unsigned*)s_sup)[t] = mm;
    }
    __syncthreads();

    // ---- phase 6: ffs-driven greedy scan (tid 0) ----
    if (tid == 0 && !s_fb) {
        if (s_ncand > NCAND) s_fb = 1;
        else {
            unsigned long long alive = (nc >= 64) ? ~0ULL : ((1ULL << nc) - 1ULL);
            while (alive && pcnt < MAXDET) {
                int s = __ffsll((long long)alive) - 1;
                alive &= ~s_sup[s];
                alive &= ~(1ULL << s);
                if (s_tinyb[s]) {
                    pk_box[pcnt] = s_sbox[s];
                    pk_cf[pcnt]  = __uint_as_float((unsigned)(s_skey[s] >> 32));
                    pcnt++;
                }
            }
            if (pcnt < MAXDET && !s_complete) s_fb = 1;
        }
    }
    __syncthreads();

    if (s_fb) {
        // ============ FALLBACK: full iterative-argmax greedy NMS (global scratch) ============
        const bool  hasconf = (s_hasconf != 0);
        const int   cap  = hasconf ? MAXDET : TOPK;
        const float thr0 = hasconf ? CONF_T : 0.0f;

        unsigned long long* fk = g_fbkey[b];
        float4*             fbx = g_fbbox[b];

        for (int i = tid; i < NBOX; i += TB) {
            float x1 = rb[i*5+0], y1 = rb[i*5+1];
            float x2 = rb[i*5+2], y2 = rb[i*5+3];
            float cf = s_conf[i];
            fbx[i] = make_float4(x1, y1, x2, y2);
            fk[i] = (cf > thr0)
                ? (((unsigned long long)__float_as_uint(cf) << 32)
                   | (unsigned long long)(0xFFFFFFFFu - (unsigned)i))
                : 0ULL;
        }
        __syncthreads();

        int   oi  = -1;
        float x1i = -1e9f, y1i = -1e9f, x2i = -1e9f, y2i = -1e9f, ai = 0.0f;
        int   cnt = 0;
        pcnt = 0;

        while (true) {
            unsigned long long part = 0ULL;
            for (int j = tid; j < NBOX; j += TB) {
                unsigned long long k = fk[j];
                if (!k) continue;
                if (j == oi) { fk[j] = 0ULL; continue; }
                float4 bb = fbx[j];
                float ix1 = fmaxf(x1i, bb.x), iy1 = fmaxf(y1i, bb.y);
                float ix2 = fminf(x2i, bb.z), iy2 = fminf(y2i, bb.w);
                float inter = fmaxf(ix2 - ix1, 0.0f) * fmaxf(iy2 - iy1, 0.0f);
                bool kill = false;
                if (inter > 0.f) {
                    float aj  = fmaxf(bb.z - bb.x, 0.0f) * fmaxf(bb.w - bb.y, 0.0f);
                    float iou = inter / (ai + aj - inter + 1e-9f);
                    kill = (iou > IOU_T);
                }
                if (kill) fk[j] = 0ULL;
                else      part = u64max(part, k);
            }
            #pragma unroll
            for (int off = 16; off; off >>= 1)
                part = u64max(part, __shfl_down_sync(0xFFFFFFFFu, part, off));
            if (lid == 0) s_wmax[wid] = part;
            __syncthreads();
            if (wid == 0) {
                unsigned long long m = (lid < 16) ? s_wmax[lid] : 0ULL;
                #pragma unroll
                for (int off = 8; off; off >>= 1)
                    m = u64max(m, __shfl_down_sync(0xFFFFFFFFu, m, off));
                if (lid == 0) s_win = m;
            }
            __syncthreads();
            unsigned long long win = s_win;
            if (win == 0ULL) break;

            oi = (int)(0xFFFFFFFFu - (unsigned)(win & 0xFFFFFFFFull));
            float4 pb = fbx[oi];
            x1i = pb.x; y1i = pb.y; x2i = pb.z; y2i = pb.w;
            ai = fmaxf(x2i - x1i, 0.0f) * fmaxf(y2i - y1i, 0.0f);
            if (x2i - x1i >= 1.0f && y2i - y1i >= 1.0f) {
                if (tid == 0) {
                    pk_box[cnt] = pb;
                    pk_cf[cnt]  = __uint_as_float((unsigned)(win >> 32));
                }
                cnt++;
                if (cnt >= cap) break;
            }
        }
        pcnt = cnt;
    }

    if (tid == 0) {
        epilogue(b, pcnt, pk_box, pk_cf, neg, out_tbox, out_keep2);
        __threadfence();
        atomicExch(&g_done[b], 1u);
    }
}

extern "C" void kernel_launch(void* const* d_in, const int* in_sizes, int n_in,
                              void* d_out, int out_size)
{
    const float* region = nullptr;
    const float* neg    = nullptr;
    for (int i = 0; i < n_in; i++) {
        if (in_sizes[i] == NIMG * NBOX * 5)        region = (const float*)d_in[i];
        else if (in_sizes[i] == NIMG * MAXDET * 5) neg    = (const float*)d_in[i];
    }

    float* out      = (float*)d_out;
    float* out_mask = out;
    float* out_tbox = out + (long)NIMG * IMG_H * IMG_W;
    float* out_k2   = out_tbox + NIMG * MAXDET * 4;

    const int grid = NIMG + NIMG * MASK_BLOCKS_PER_IMG;   // 16 + 512 = 528
    fused_kernel<<<grid, TB>>>(region, neg, out_mask, out_tbox, out_k2);
}